// round 5
// baseline (speedup 1.0000x reference)
#include <cuda_runtime.h>
#include <cuda_fp16.h>
#include <cstdint>

// adder2d: out[b,f,l] = -sum_{c,kh,kw} |W[f,c,kh,kw] - xpad[b,c,...]|
// fp16x2 inner math (packed dim = 2 filters), fp32 promotion via atomics.
// Grid: 8 fgroups(16 filters) x 16 batches x 32 channel-chunks(4ch) = 4096 CTAs.
// CTA 224 thr: t<112 -> pairs 0..3 (filters 0..7), t>=112 -> pairs 4..7 (8..15).
// Per thread: 7 outputs x 4 pairs, fp16x2 accs (36 terms max -> err ~2e-4 rel).
// x tile dup (v,v) fp16x2, double-buffered, row stride 36 (conflict-free).

#define BATCH 16
#define CIN   128
#define HW    28
#define LSP   784
#define FOUT  128
#define NT    224
#define CPC   4           // channels per CTA
#define NCHQ  32          // channel chunks
#define SROW  36          // tile row stride (fp16x2 elems); 36%32==4 -> conflict-free
#define TROWS 30

typedef unsigned int u32;

// acc2 += | w2 - p2 |   (fp16x2: HFMA2 + LOP3 + HADD2)
__device__ __forceinline__ void absdiff_acc(u32& acc, u32 p2, u32 negone, u32 w2) {
    asm("{\n\t"
        ".reg .b32 d;\n\t"
        "fma.rn.f16x2 d, %1, %2, %3;\n\t"
        "and.b32 d, d, 0x7FFF7FFF;\n\t"
        "add.rn.f16x2 %0, %0, d;\n\t"
        "}"
        : "+r"(acc) : "r"(p2), "r"(negone), "r"(w2));
}

__global__ void zero_out_kernel(float4* o) {
    o[(size_t)blockIdx.x * 1024 + threadIdx.x] = make_float4(0.f, 0.f, 0.f, 0.f);
}

__global__ __launch_bounds__(NT, 4)
void adder2d_kernel(const float* __restrict__ x,
                    const float* __restrict__ Wt,
                    float* __restrict__ out) {
    __shared__ u32 xs[2][TROWS * SROW];      // dup (v,v) fp16x2 tiles, 8640 B
    __shared__ u32 ws[CPC * 9 * 8];          // [c][kk][pair0..7] fp16x2, 1152 B

    const int b     = blockIdx.y;
    const int fbase = blockIdx.x * 16;       // 16 filters per CTA
    const int cq    = blockIdx.z;            // 4-channel chunk
    const int t     = threadIdx.x;
    const int tl    = (t < 112) ? t : (t - 112);
    const int g     = (t < 112) ? 0 : 4;     // pair base: pairs g..g+3
    const int h     = tl >> 2;               // output row 0..27
    const int q     = tl & 3;                // col group: cols 7q..7q+6

    // zero both tiles (halo stays zero)
    for (int i = t; i < 2 * TROWS * SROW; i += NT)
        (&xs[0][0])[i] = 0u;

    // stage W pairs: 4ch x 9kk x 8pairs, fp16x2 (w_f0, w_f1)
    {
        const float* Wb = Wt + (size_t)fbase * (CIN * 9) + (size_t)cq * CPC * 9;
        for (int i = t; i < CPC * 9 * 8; i += NT) {
            int p  = i & 7;                  // pair 0..7
            int ck = i >> 3;                 // c*9 + kk
            const float* wp = Wb + (size_t)(2 * p) * (CIN * 9) + ck;
            __half2 hw = __floats2half2_rn(wp[0], wp[CIN * 9]);  // (lo=f0, hi=f1)
            ws[ck * 8 + p] = *reinterpret_cast<u32*>(&hw);
        }
    }

    // fill mapping: thread t stores l = t + 224*j, j=0..2 (+3 for t<112)
    int offs_sts[4];
#pragma unroll
    for (int j = 0; j < 4; ++j) {
        int l = t + NT * j;
        if (l < LSP) {
            int hh = l / HW;
            int ww = l - hh * HW;
            offs_sts[j] = (hh + 1) * SROW + (ww + 1);
        } else offs_sts[j] = 0;
    }

    const float* xg = x + ((size_t)b * CIN + (size_t)cq * CPC) * LSP;
    float r[4];
#pragma unroll
    for (int j = 0; j < 3; ++j) r[j] = xg[t + NT * j];
    if (t < 112) r[3] = xg[t + NT * 3];

    u32 acc[4][7];
#pragma unroll
    for (int p = 0; p < 4; ++p)
#pragma unroll
        for (int j = 0; j < 7; ++j) acc[p][j] = 0u;

    const u32 NEG1 = 0xBC00BC00u;            // (-1.h, -1.h)
    const int cb   = h * SROW + 7 * q;

    __syncthreads();  // zeroing + ws visible

#pragma unroll
    for (int ch = 0; ch < CPC; ++ch) {
        const int buf = ch & 1;
        // store current channel as dup fp16x2
#pragma unroll
        for (int j = 0; j < 3; ++j) {
            __half2 hv = __floats2half2_rn(r[j], r[j]);
            xs[buf][offs_sts[j]] = *reinterpret_cast<u32*>(&hv);
        }
        if (t < 112) {
            __half2 hv = __floats2half2_rn(r[3], r[3]);
            xs[buf][offs_sts[3]] = *reinterpret_cast<u32*>(&hv);
        }
        // prefetch next channel
        if (ch + 1 < CPC) {
            const float* xn = xg + (size_t)(ch + 1) * LSP;
#pragma unroll
            for (int j = 0; j < 3; ++j) r[j] = xn[t + NT * j];
            if (t < 112) r[3] = xn[t + NT * 3];
        }
        __syncthreads();

        const u32* wrow = ws + ch * 72;      // (kk)*8 + pair
#pragma unroll
        for (int kh = 0; kh < 3; ++kh) {
            u32 xv[9];
#pragma unroll
            for (int i = 0; i < 9; ++i)
                xv[i] = xs[buf][cb + kh * SROW + i];
#pragma unroll
            for (int kw = 0; kw < 3; ++kw) {
                uint4 wv = *reinterpret_cast<const uint4*>(&wrow[(kh * 3 + kw) * 8 + g]);
#pragma unroll
                for (int j = 0; j < 7; ++j) {
                    absdiff_acc(acc[0][j], xv[j + kw], NEG1, wv.x);
                    absdiff_acc(acc[1][j], xv[j + kw], NEG1, wv.y);
                    absdiff_acc(acc[2][j], xv[j + kw], NEG1, wv.z);
                    absdiff_acc(acc[3][j], xv[j + kw], NEG1, wv.w);
                }
            }
        }
    }

    // epilogue: promote fp16x2 -> 2x fp32, atomic-accumulate negated partials
    float* ob = out + ((size_t)b * FOUT + fbase) * LSP + h * HW + 7 * q;
#pragma unroll
    for (int p = 0; p < 4; ++p) {
        int f0 = 2 * (g + p);
        float* o0 = ob + (size_t)f0 * LSP;
        float* o1 = o0 + LSP;
#pragma unroll
        for (int j = 0; j < 7; ++j) {
            float2 v = __half22float2(*reinterpret_cast<__half2*>(&acc[p][j]));
            atomicAdd(&o0[j], -v.x);
            atomicAdd(&o1[j], -v.y);
        }
    }
}

extern "C" void kernel_launch(void* const* d_in, const int* in_sizes, int n_in,
                              void* d_out, int out_size) {
    const float* x = (const float*)d_in[0];
    const float* W = (const float*)d_in[1];
    if (n_in >= 2 && in_sizes[0] == FOUT * CIN * 9 && in_sizes[1] == BATCH * CIN * LSP) {
        const float* tmp = x; x = W; W = tmp;
    }
    float* out = (float*)d_out;

    // out = 16*128*784 floats = 401408 float4 = 392 * 1024
    zero_out_kernel<<<392, 1024>>>((float4*)out);

    dim3 grid(FOUT / 16, BATCH, NCHQ);   // 8 x 16 x 32 = 4096 CTAs
    adder2d_kernel<<<grid, NT>>>(x, W, out);
}

// round 7
// speedup vs baseline: 1.4079x; 1.4079x over previous
#include <cuda_runtime.h>
#include <cuda_fp16.h>
#include <cstdint>

// adder2d: out[b,f,l] = -sum_{c,kh,kw} |W[f,c,kh,kw] - xpad[b,c,...]|
// fp16x2 inner math (packed dim = 2 filters), fp32 promotion via gmem RED.
// Grid: 8 fgroups(16 filters) x 16 batches x 8 chunks(16 ch) = 1024 CTAs.
// CTA 224 thr: t<112 -> pairs 0..3 (filters 0..7), t>=112 -> pairs 4..7.
// Per thread: 7 outputs x 4 pairs; fp16 accs over 144 terms (~3e-4 rel err).
// x tile dup (v,v) fp16x2, double-buffered, row stride 36 u32 (conflict-free
// for warps 0-2,4-6; warp 3 takes a benign 2-way on xv).

#define BATCH 16
#define CIN   128
#define HW    28
#define LSP   784
#define FOUT  128
#define NT    224
#define CPC   16          // channels per CTA
#define NCHQ  8           // channel chunks
#define SROW  36          // tile row stride (u32 elems)
#define TROWS 30

typedef unsigned int u32;

// acc2 += | w2 - p2 |   (HFMA2 + LOP3 + HADD2 : 2 fma-pipe + 1 alu-pipe)
__device__ __forceinline__ void absdiff_acc(u32& acc, u32 p2, u32 negone, u32 w2) {
    asm("{\n\t"
        ".reg .b32 d;\n\t"
        "fma.rn.f16x2 d, %1, %2, %3;\n\t"
        "and.b32 d, d, 0x7FFF7FFF;\n\t"
        "add.rn.f16x2 %0, %0, d;\n\t"
        "}"
        : "+r"(acc) : "r"(p2), "r"(negone), "r"(w2));
}

__global__ void zero_out_kernel(float4* o) {
    o[(size_t)blockIdx.x * 1024 + threadIdx.x] = make_float4(0.f, 0.f, 0.f, 0.f);
}

__global__ __launch_bounds__(NT, 4)
void adder2d_kernel(const float* __restrict__ x,
                    const float* __restrict__ Wt,
                    float* __restrict__ out) {
    __shared__ u32 xs[2][TROWS * SROW];      // dup (v,v) fp16x2 tiles, 8640 B
    __shared__ u32 ws[CPC * 9 * 8];          // [c][kk][pair0..7] fp16x2, 4608 B

    const int b     = blockIdx.y;
    const int fbase = blockIdx.x * 16;       // 16 filters per CTA
    const int cq    = blockIdx.z;            // 16-channel chunk
    const int t     = threadIdx.x;
    const int tl    = (t < 112) ? t : (t - 112);
    const int g     = (t < 112) ? 0 : 4;     // pair base: pairs g..g+3
    const int h     = tl >> 2;               // output row 0..27
    const int q     = tl & 3;                // col group: cols 7q..7q+6

    // zero both tiles (halo stays zero; interior rewritten per channel)
    for (int i = t; i < 2 * TROWS * SROW; i += NT)
        (&xs[0][0])[i] = 0u;

    // stage W pairs: 16ch x 9kk x 8pairs, fp16x2 (w_f0, w_f1)
    {
        const float* Wb = Wt + (size_t)fbase * (CIN * 9) + (size_t)cq * CPC * 9;
        for (int i = t; i < CPC * 9 * 8; i += NT) {
            int p  = i & 7;                  // pair 0..7
            int ck = i >> 3;                 // c*9 + kk
            const float* wp = Wb + (size_t)(2 * p) * (CIN * 9) + ck;
            __half2 hw = __floats2half2_rn(wp[0], wp[CIN * 9]);  // (lo=f0, hi=f1)
            ws[ck * 8 + p] = *reinterpret_cast<u32*>(&hw);
        }
    }

    // fill mapping: thread t stores l = t + 224*j, j=0..2 (+3 for t<112)
    int offs_sts[4];
#pragma unroll
    for (int j = 0; j < 4; ++j) {
        int l = t + NT * j;
        if (l < LSP) {
            int hh = l / HW;
            int ww = l - hh * HW;
            offs_sts[j] = (hh + 1) * SROW + (ww + 1);
        } else offs_sts[j] = 0;
    }

    const float* xg = x + ((size_t)b * CIN + (size_t)cq * CPC) * LSP;
    float r[4];
#pragma unroll
    for (int j = 0; j < 3; ++j) r[j] = xg[t + NT * j];
    if (t < 112) r[3] = xg[t + NT * 3];

    u32 acc[4][7];
#pragma unroll
    for (int p = 0; p < 4; ++p)
#pragma unroll
        for (int j = 0; j < 7; ++j) acc[p][j] = 0u;

    const u32 NEG1 = 0xBC00BC00u;            // (-1.h, -1.h)
    const int cb   = h * SROW + 7 * q;

    __syncthreads();  // zeroing + ws visible

#pragma unroll 1
    for (int ch = 0; ch < CPC; ++ch) {
        const int buf = ch & 1;
        // store current channel as dup fp16x2
#pragma unroll
        for (int j = 0; j < 3; ++j) {
            __half2 hv = __floats2half2_rn(r[j], r[j]);
            xs[buf][offs_sts[j]] = *reinterpret_cast<u32*>(&hv);
        }
        if (t < 112) {
            __half2 hv = __floats2half2_rn(r[3], r[3]);
            xs[buf][offs_sts[3]] = *reinterpret_cast<u32*>(&hv);
        }
        // prefetch next channel
        if (ch + 1 < CPC) {
            const float* xn = xg + (size_t)(ch + 1) * LSP;
#pragma unroll
            for (int j = 0; j < 3; ++j) r[j] = xn[t + NT * j];
            if (t < 112) r[3] = xn[t + NT * 3];
        }
        __syncthreads();

        const u32* wrow = ws + ch * 72;      // (kk)*8 + pair
#pragma unroll
        for (int kh = 0; kh < 3; ++kh) {
            u32 xv[9];
#pragma unroll
            for (int i = 0; i < 9; ++i)
                xv[i] = xs[buf][cb + kh * SROW + i];
#pragma unroll
            for (int kw = 0; kw < 3; ++kw) {
                uint4 wv = *reinterpret_cast<const uint4*>(&wrow[(kh * 3 + kw) * 8 + g]);
#pragma unroll
                for (int j = 0; j < 7; ++j) {
                    absdiff_acc(acc[0][j], xv[j + kw], NEG1, wv.x);
                    absdiff_acc(acc[1][j], xv[j + kw], NEG1, wv.y);
                    absdiff_acc(acc[2][j], xv[j + kw], NEG1, wv.z);
                    absdiff_acc(acc[3][j], xv[j + kw], NEG1, wv.w);
                }
            }
        }
    }

    // epilogue: promote fp16x2 -> 2x fp32, RED-accumulate negated partials
    float* ob = out + ((size_t)b * FOUT + fbase) * LSP + h * HW + 7 * q;
#pragma unroll
    for (int p = 0; p < 4; ++p) {
        int f0 = 2 * (g + p);
        float* o0 = ob + (size_t)f0 * LSP;
        float* o1 = o0 + LSP;
#pragma unroll
        for (int j = 0; j < 7; ++j) {
            float2 v = __half22float2(*reinterpret_cast<__half2*>(&acc[p][j]));
            atomicAdd(&o0[j], -v.x);
            atomicAdd(&o1[j], -v.y);
        }
    }
}

extern "C" void kernel_launch(void* const* d_in, const int* in_sizes, int n_in,
                              void* d_out, int out_size) {
    const float* x = (const float*)d_in[0];
    const float* W = (const float*)d_in[1];
    if (n_in >= 2 && in_sizes[0] == FOUT * CIN * 9 && in_sizes[1] == BATCH * CIN * LSP) {
        const float* tmp = x; x = W; W = tmp;
    }
    float* out = (float*)d_out;

    // out = 16*128*784 floats = 401408 float4 = 392 * 1024
    zero_out_kernel<<<392, 1024>>>((float4*)out);

    dim3 grid(FOUT / 16, BATCH, NCHQ);   // 8 x 16 x 8 = 1024 CTAs
    adder2d_kernel<<<grid, NT>>>(x, W, out);
}

// round 8
// speedup vs baseline: 1.4347x; 1.0190x over previous
#include <cuda_runtime.h>
#include <cuda_fp16.h>
#include <cstdint>

// adder2d: out[b,f,l] = -sum_{c,kh,kw} |W[f,c,kh,kw] - xpad[b,c,...]|
// fp16x2 inner math (packed = 2 filters), fp32 promotion via gmem RED.
// Grid: 8 fgroups(16 filters) x 16 batches x 8 chunks(16 ch) = 1024 CTAs.
// CTA 224 thr, occ 5 (regs capped 58): t<112 -> pairs 0..3, t>=112 -> 4..7.
// W pre-packed once into [c*9][fpair] fp16x2 by prep kernel (coalesced staging).

#define BATCH 16
#define CIN   128
#define HW    28
#define LSP   784
#define FOUT  128
#define NT    224
#define CPC   16
#define NCHQ  8
#define SROW  36
#define TROWS 30
#define NFP   (FOUT / 2)      // 64 filter pairs

typedef unsigned int u32;

// packed W: g_wpack[(c*9 + kk)*NFP + fp] = (half(W[2fp,c,kk]), half(W[2fp+1,c,kk]))
__device__ u32 g_wpack[CIN * 9 * NFP];

// acc2 += | w2 - p2 |   (HFMA2 + LOP3 + HADD2 : 2 fma-pipe + 1 alu-pipe)
__device__ __forceinline__ void absdiff_acc(u32& acc, u32 p2, u32 negone, u32 w2) {
    asm("{\n\t"
        ".reg .b32 d;\n\t"
        "fma.rn.f16x2 d, %1, %2, %3;\n\t"
        "and.b32 d, d, 0x7FFF7FFF;\n\t"
        "add.rn.f16x2 %0, %0, d;\n\t"
        "}"
        : "+r"(acc) : "r"(p2), "r"(negone), "r"(w2));
}

__global__ void zero_out_kernel(float4* o) {
    o[(size_t)blockIdx.x * 1024 + threadIdx.x] = make_float4(0.f, 0.f, 0.f, 0.f);
}

__global__ void prep_w_kernel(const float* __restrict__ Wt) {
    int i = blockIdx.x * 256 + threadIdx.x;     // i over CIN*9*NFP = 73728
    if (i >= CIN * 9 * NFP) return;
    int fp  = i & (NFP - 1);                    // fastest: filter pair
    int ck  = i >> 6;                           // c*9 + kk
    const float* wp = Wt + (size_t)(2 * fp) * (CIN * 9) + ck;
    __half2 hw = __floats2half2_rn(wp[0], wp[CIN * 9]);
    g_wpack[(size_t)ck * NFP + fp] = *reinterpret_cast<u32*>(&hw);
}

__global__ __launch_bounds__(NT, 5)
void adder2d_kernel(const float* __restrict__ x,
                    float* __restrict__ out) {
    __shared__ u32 xs[2][TROWS * SROW];   // dup (v,v) fp16x2 tiles, 8640 B
    __shared__ u32 ws[CPC * 9 * 8];       // [c*9+kk][pair0..7] fp16x2, 4608 B

    const int b     = blockIdx.y;
    const int fp0   = blockIdx.x * 8;     // first filter pair of CTA (8 pairs)
    const int cq    = blockIdx.z;
    const int t     = threadIdx.x;
    const int tl    = (t < 112) ? t : (t - 112);
    const int g     = (t < 112) ? 0 : 4;  // pair base within CTA
    const int h     = tl >> 2;
    const int q     = tl & 3;

    // zero both tiles (halo stays zero)
    for (int i = t; i < 2 * TROWS * SROW; i += NT)
        (&xs[0][0])[i] = 0u;

    // stage pre-packed W: 16ch x 9kk x 8 pairs, coalesced-ish from g_wpack
    {
        const u32* wp = g_wpack + (size_t)(cq * CPC * 9) * NFP + fp0;
        for (int i = t; i < CPC * 9 * 8; i += NT) {
            int p  = i & 7;
            int ck = i >> 3;
            ws[i] = wp[(size_t)ck * NFP + p];
        }
    }

    // STS offsets packed 2 per u32 (each <= 1073 < 2^16)
    u32 offsA, offsB;
    {
        u32 o[4];
#pragma unroll
        for (int j = 0; j < 4; ++j) {
            int l = t + NT * j;
            if (l < LSP) {
                int hh = l / HW;
                int ww = l - hh * HW;
                o[j] = (hh + 1) * SROW + (ww + 1);
            } else o[j] = 0;
        }
        offsA = o[0] | (o[1] << 16);
        offsB = o[2] | (o[3] << 16);
    }

    const float* xg = x + ((size_t)b * CIN + (size_t)cq * CPC) * LSP;
    float r[4];
#pragma unroll
    for (int j = 0; j < 3; ++j) r[j] = xg[t + NT * j];
    if (t < 112) r[3] = xg[t + NT * 3];

    u32 acc[4][7];
#pragma unroll
    for (int p = 0; p < 4; ++p)
#pragma unroll
        for (int j = 0; j < 7; ++j) acc[p][j] = 0u;

    const u32 NEG1 = 0xBC00BC00u;
    const int cb   = h * SROW + 7 * q;

    __syncthreads();

#pragma unroll 1
    for (int ch = 0; ch < CPC; ++ch) {
        const int buf = ch & 1;
        // store current channel as dup fp16x2
        {
            __half2 h0 = __floats2half2_rn(r[0], r[0]);
            __half2 h1 = __floats2half2_rn(r[1], r[1]);
            __half2 h2 = __floats2half2_rn(r[2], r[2]);
            xs[buf][offsA & 0xFFFF]  = *reinterpret_cast<u32*>(&h0);
            xs[buf][offsA >> 16]     = *reinterpret_cast<u32*>(&h1);
            xs[buf][offsB & 0xFFFF]  = *reinterpret_cast<u32*>(&h2);
            if (t < 112) {
                __half2 h3 = __floats2half2_rn(r[3], r[3]);
                xs[buf][offsB >> 16] = *reinterpret_cast<u32*>(&h3);
            }
        }
        // prefetch next channel
        if (ch + 1 < CPC) {
            const float* xn = xg + (size_t)(ch + 1) * LSP;
#pragma unroll
            for (int j = 0; j < 3; ++j) r[j] = xn[t + NT * j];
            if (t < 112) r[3] = xn[t + NT * 3];
        }
        __syncthreads();

        const u32* wrow = ws + ch * 72;
#pragma unroll
        for (int kh = 0; kh < 3; ++kh) {
            u32 xv[9];
#pragma unroll
            for (int i = 0; i < 9; ++i)
                xv[i] = xs[buf][cb + kh * SROW + i];
#pragma unroll
            for (int kw = 0; kw < 3; ++kw) {
                uint4 wv = *reinterpret_cast<const uint4*>(&wrow[(kh * 3 + kw) * 8 + g]);
#pragma unroll
                for (int j = 0; j < 7; ++j) {
                    absdiff_acc(acc[0][j], xv[j + kw], NEG1, wv.x);
                    absdiff_acc(acc[1][j], xv[j + kw], NEG1, wv.y);
                    absdiff_acc(acc[2][j], xv[j + kw], NEG1, wv.z);
                    absdiff_acc(acc[3][j], xv[j + kw], NEG1, wv.w);
                }
            }
        }
    }

    // epilogue: promote fp16x2 -> 2x fp32, RED-accumulate negated partials
    float* ob = out + ((size_t)b * FOUT + 2 * fp0) * LSP + h * HW + 7 * q;
#pragma unroll
    for (int p = 0; p < 4; ++p) {
        int f0 = 2 * (g + p);
        float* o0 = ob + (size_t)f0 * LSP;
        float* o1 = o0 + LSP;
#pragma unroll
        for (int j = 0; j < 7; ++j) {
            float2 v = __half22float2(*reinterpret_cast<__half2*>(&acc[p][j]));
            atomicAdd(&o0[j], -v.x);
            atomicAdd(&o1[j], -v.y);
        }
    }
}

extern "C" void kernel_launch(void* const* d_in, const int* in_sizes, int n_in,
                              void* d_out, int out_size) {
    const float* x = (const float*)d_in[0];
    const float* W = (const float*)d_in[1];
    if (n_in >= 2 && in_sizes[0] == FOUT * CIN * 9 && in_sizes[1] == BATCH * CIN * LSP) {
        const float* tmp = x; x = W; W = tmp;
    }
    float* out = (float*)d_out;

    prep_w_kernel<<<(CIN * 9 * NFP + 255) / 256, 256>>>(W);
    zero_out_kernel<<<392, 1024>>>((float4*)out);   // 16*128*784 f32 = 392*1024 f4

    dim3 grid(FOUT / 16, BATCH, NCHQ);   // 8 x 16 x 8 = 1024 CTAs
    adder2d_kernel<<<grid, NT>>>(x, out);
}